// round 13
// baseline (speedup 1.0000x reference)
#include <cuda_runtime.h>
#include <cuda_fp16.h>
#include <math.h>
#include <stdint.h>

#define BATCH 2
#define SEQ 2048
#define DIM 2048
#define HEADS 16
#define HD 128
#define DI 2048           /* HEADS*HD */
#define MTOT (BATCH*SEQ)  /* 4096 */

// ---------------- scratch (device globals: allocation-free rule) ------------
__device__ float g_rinv[4][DIM];     // 0:Wq rows 1:Wk rows 2:Wv rows 3:Wout cols
__device__ float g_colpart[16][DIM];
__device__ __half g_x16[(size_t)MTOT * DIM];
__device__ __half g_w16[4][(size_t)DIM * DIM];   // q,k,v,out
__device__ __half g_q16[(size_t)MTOT * DI];
__device__ __half g_k16[(size_t)MTOT * DI];
__device__ __half g_v16[(size_t)MTOT * DI];
__device__ __half g_o16[(size_t)MTOT * DI];

// ============================ PTX helpers (sm_80+ portable) =================
__device__ __forceinline__ uint32_t smem_u32(const void* p) {
    uint32_t a;
    asm("{ .reg .u64 t; cvta.to.shared.u64 t, %1; cvt.u32.u64 %0, t; }"
        : "=r"(a) : "l"(p));
    return a;
}

__device__ __forceinline__ void cp16(uint32_t saddr, const void* g) {
    asm volatile("cp.async.cg.shared.global [%0], [%1], 16;"
                 :: "r"(saddr), "l"(g) : "memory");
}
#define CP_COMMIT() asm volatile("cp.async.commit_group;" ::: "memory")
#define CP_WAIT(n)  asm volatile("cp.async.wait_group %0;" :: "n"(n) : "memory")

#define LDSM_X4(r, addr) \
    asm volatile("ldmatrix.sync.aligned.m8n8.x4.shared.b16 {%0,%1,%2,%3}, [%4];" \
        : "=r"((r)[0]), "=r"((r)[1]), "=r"((r)[2]), "=r"((r)[3]) : "r"(addr))

#define LDSM_X4_T(r, addr) \
    asm volatile("ldmatrix.sync.aligned.m8n8.x4.trans.shared.b16 {%0,%1,%2,%3}, [%4];" \
        : "=r"((r)[0]), "=r"((r)[1]), "=r"((r)[2]), "=r"((r)[3]) : "r"(addr))

#define MMA16816H(d, a, b0, b1) \
    asm volatile("mma.sync.aligned.m16n8k16.row.col.f32.f16.f16.f32 " \
        "{%0,%1,%2,%3}, {%4,%5,%6,%7}, {%8,%9}, {%0,%1,%2,%3};" \
        : "+f"((d)[0]), "+f"((d)[1]), "+f"((d)[2]), "+f"((d)[3]) \
        : "r"((a)[0]), "r"((a)[1]), "r"((a)[2]), "r"((a)[3]), "r"(b0), "r"(b1))

__device__ __forceinline__ uint32_t pack2h(float a, float b) {
    uint32_t r;
    asm("cvt.rn.f16x2.f32 %0, %1, %2;" : "=r"(r) : "f"(b), "f"(a));
    return r;
}
__device__ __forceinline__ float ex2f(float x) {
    float r;
    asm("ex2.approx.ftz.f32 %0, %1;" : "=f"(r) : "f"(x));
    return r;
}

// =================== fused prep: all converts + norms in ONE kernel ==========
__global__ void __launch_bounds__(256) prep_fused(
    const float* __restrict__ x, const float* __restrict__ Wq,
    const float* __restrict__ Wk, const float* __restrict__ Wv,
    const float* __restrict__ Wout)
{
    __shared__ float red[8];
    const int bid = blockIdx.x, tid = threadIdx.x;
    if (bid < 8192) {                       // x convert
        const int i = bid * 256 + tid;
        float4 v = ((const float4*)x)[i];
        uint32_t* o = (uint32_t*)g_x16;
        o[2 * i] = pack2h(v.x, v.y);
        o[2 * i + 1] = pack2h(v.z, v.w);
    } else if (bid < 14336) {               // Wq/Wk/Wv rows + norms
        const int t = bid - 8192;
        const int sel = t >> 11, row = t & 2047;
        const float* W = sel == 0 ? Wq : (sel == 1 ? Wk : Wv);
        const float4* p = (const float4*)(W + (size_t)row * DIM);
        uint32_t* op = (uint32_t*)(&g_w16[sel][(size_t)row * DIM]);
        float s = 0.f;
        #pragma unroll
        for (int i = tid; i < DIM / 4; i += 256) {
            float4 v = p[i];
            s += v.x * v.x + v.y * v.y + v.z * v.z + v.w * v.w;
            op[2 * i] = pack2h(v.x, v.y);
            op[2 * i + 1] = pack2h(v.z, v.w);
        }
        #pragma unroll
        for (int off = 16; off; off >>= 1) s += __shfl_xor_sync(0xffffffffu, s, off);
        if ((tid & 31) == 0) red[tid >> 5] = s;
        __syncthreads();
        if (tid == 0) {
            float tt = 0.f;
            #pragma unroll
            for (int i = 0; i < 8; i++) tt += red[i];
            g_rinv[sel][row] = 1.f / fmaxf(sqrtf(tt), 1e-12f);
        }
    } else if (bid < 18432) {               // Wout convert
        const int i = (bid - 14336) * 256 + tid;
        float4 v = ((const float4*)Wout)[i];
        uint32_t* o = (uint32_t*)(&g_w16[3][0]);
        o[2 * i] = pack2h(v.x, v.y);
        o[2 * i + 1] = pack2h(v.z, v.w);
    } else {                                 // colnorm partials
        const int t = bid - 18432;           // 0..127
        const int col = (t & 7) * 256 + tid;
        const int r0 = (t >> 3) * 128;
        float s = 0.f;
        for (int r = 0; r < 128; ++r) {
            float v = Wout[(size_t)(r0 + r) * DI + col];
            s += v * v;
        }
        g_colpart[t >> 3][col] = s;
    }
}

__global__ void colnorm_fin() {
    int c = blockIdx.x * 256 + threadIdx.x;
    float s = 0.f;
    #pragma unroll
    for (int i = 0; i < 16; ++i) s += g_colpart[i][c];
    g_rinv[3][c] = 1.f / fmaxf(sqrtf(s), 1e-12f);
}

// =================== fp16 single-pass NT GEMM, 128x128x64 CTA tiles ==========
// 128 thr / 4 warps (wm 0..1 x wn 0..1), warp tile 64x64 -> 4 MMA per LDSM
// (was 2.67). 3-stage cp.async, 2 CTA/SM, one sync per k-tile.
#define GS_MAT 16384
#define GS_STAGE 32768
#define GS_NKT (DIM / 64)   /* 32 */

struct GAcc { float a[4][8][4]; };   // [m16 block][n8 block][frag]

__device__ __forceinline__ void gemm_mainloop(
    const __half* __restrict__ Ag, const __half* __restrict__ Bg,
    uint32_t sb, int tid, int mbase, int nbase, GAcc& acc)
{
    const int wid = tid >> 5, lane = tid & 31;
    const int wm = wid >> 1, wn = wid & 1;

    auto load_stage = [&](int kt, int buf) {
        const uint32_t st = sb + buf * GS_STAGE;
        const int koff = kt * 64;
        #pragma unroll
        for (int h = 0; h < 8; ++h) {
            const int cid = tid + h * 128;
            const int r = cid >> 3, c = cid & 7;
            const uint32_t aoff = ((c >> 1) << 12) + ((r >> 4) << 9) +
                (((r & 7) + ((r >> 3) & 1) * 8 + (c & 1) * 16) << 4);
            const uint32_t boff = ((c >> 1) << 12) + ((r >> 4) << 9) +
                (((r & 7) + (c & 1) * 8 + ((r >> 3) & 1) * 16) << 4);
            cp16(st + aoff, Ag + (size_t)(mbase + r) * DIM + koff + c * 8);
            cp16(st + GS_MAT + boff, Bg + (size_t)(nbase + r) * DIM + koff + c * 8);
        }
    };

    #pragma unroll
    for (int i = 0; i < 4; i++)
        #pragma unroll
        for (int j = 0; j < 8; j++)
            #pragma unroll
            for (int t = 0; t < 4; t++) acc.a[i][j][t] = 0.f;

    load_stage(0, 0); CP_COMMIT();
    load_stage(1, 1); CP_COMMIT();

    for (int kt = 0; kt < GS_NKT; ++kt) {
        CP_WAIT(1);          // stage kt complete
        __syncthreads();     // visible; compute(kt-1) done
        if (kt + 2 < GS_NKT) load_stage(kt + 2, (kt + 2) % 3);
        CP_COMMIT();         // always commit (empty ok)
        const uint32_t stg = sb + (kt % 3) * GS_STAGE;
        #pragma unroll
        for (int s = 0; s < 4; ++s) {   // four k16 slabs per k-tile
            uint32_t a[4][4], b[4][4];
            #pragma unroll
            for (int g = 0; g < 4; ++g)
                LDSM_X4(a[g], stg + (s << 12) + (((wm * 4 + g)) << 9) + lane * 16);
            #pragma unroll
            for (int g = 0; g < 4; ++g)
                LDSM_X4(b[g], stg + GS_MAT + (s << 12) + (((wn * 4 + g)) << 9) + lane * 16);
            #pragma unroll
            for (int ai = 0; ai < 4; ++ai)
                #pragma unroll
                for (int bg = 0; bg < 4; ++bg) {
                    MMA16816H(acc.a[ai][2 * bg],     a[ai], b[bg][0], b[bg][1]);
                    MMA16816H(acc.a[ai][2 * bg + 1], a[ai], b[bg][2], b[bg][3]);
                }
        }
    }
    __syncthreads();
}

// merged QKV projection: blockIdx.z selects weight + epilogue flavor.
__global__ void __launch_bounds__(128) gemm_qkv(const float* __restrict__ qks) {
    extern __shared__ char smem[];
    const uint32_t sb = smem_u32(smem);
    const int tid = threadIdx.x;
    const int wid = tid >> 5, lane = tid & 31;
    const int wm = wid >> 1, wn = wid & 1;
    const int mbase = blockIdx.y * 128, nbase = blockIdx.x * 128;
    const int sel = blockIdx.z;

    GAcc acc;
    gemm_mainloop(g_x16, g_w16[sel], sb, tid, mbase, nbase, acc);

    // weight row-norm reciprocal (per output column)
    {
        const float* rinv = g_rinv[sel];
        #pragma unroll
        for (int j = 0; j < 8; ++j) {
            const int col = nbase + wn * 64 + j * 8 + (lane & 3) * 2;
            const float s0 = rinv[col], s1 = rinv[col + 1];
            #pragma unroll
            for (int i = 0; i < 4; ++i) {
                acc.a[i][j][0] *= s0; acc.a[i][j][1] *= s1;
                acc.a[i][j][2] *= s0; acc.a[i][j][3] *= s1;
            }
        }
    }
    if (sel < 2) {
        // per-row l2 norm over this CTA's 128 cols (= one head).
        // thread owns 8 row-slots: (ai, half i) -> row wm*64+ai*16+(lane>>2)+i*8
        float ssq[4][2];
        #pragma unroll
        for (int ai = 0; ai < 4; ++ai) {
            ssq[ai][0] = 0.f; ssq[ai][1] = 0.f;
            #pragma unroll
            for (int j = 0; j < 8; ++j) {
                ssq[ai][0] += acc.a[ai][j][0] * acc.a[ai][j][0] +
                              acc.a[ai][j][1] * acc.a[ai][j][1];
                ssq[ai][1] += acc.a[ai][j][2] * acc.a[ai][j][2] +
                              acc.a[ai][j][3] * acc.a[ai][j][3];
            }
        }
        #pragma unroll
        for (int ai = 0; ai < 4; ++ai)
            #pragma unroll
            for (int i = 0; i < 2; ++i) {
                ssq[ai][i] += __shfl_xor_sync(0xffffffffu, ssq[ai][i], 1);
                ssq[ai][i] += __shfl_xor_sync(0xffffffffu, ssq[ai][i], 2);
            }
        float* red = (float*)smem;   // reuse pipeline smem: [2][128]
        if ((lane & 3) == 0) {
            #pragma unroll
            for (int ai = 0; ai < 4; ++ai)
                #pragma unroll
                for (int i = 0; i < 2; ++i)
                    red[wn * 128 + wm * 64 + ai * 16 + (lane >> 2) + i * 8] = ssq[ai][i];
        }
        __syncthreads();
        float rn_[4][2];
        #pragma unroll
        for (int ai = 0; ai < 4; ++ai)
            #pragma unroll
            for (int i = 0; i < 2; ++i) {
                const int lr = wm * 64 + ai * 16 + (lane >> 2) + i * 8;
                rn_[ai][i] = 1.f / fmaxf(sqrtf(red[lr] + red[128 + lr]), 1e-12f);
            }
        #pragma unroll
        for (int ai = 0; ai < 4; ++ai)
            #pragma unroll
            for (int j = 0; j < 8; ++j) {
                acc.a[ai][j][0] *= rn_[ai][0]; acc.a[ai][j][1] *= rn_[ai][0];
                acc.a[ai][j][2] *= rn_[ai][1]; acc.a[ai][j][3] *= rn_[ai][1];
            }
    }
    __half* Ch = sel == 0 ? g_q16 : (sel == 1 ? g_k16 : g_v16);
    #pragma unroll
    for (int j = 0; j < 8; ++j) {
        const int col = nbase + wn * 64 + j * 8 + (lane & 3) * 2;
        float qm0 = 1.f, qm1 = 1.f;
        if (sel == 0) {
            // DIM * sqrt(HD) * log2(e)  (softmax uses ex2)
            const float C = 23170.475005920826f * 1.4426950408889634f;
            qm0 = qks[col] * C;
            qm1 = qks[col + 1] * C;
        }
        #pragma unroll
        for (int ai = 0; ai < 4; ++ai) {
            const int row = mbase + wm * 64 + ai * 16 + (lane >> 2);
            *(uint32_t*)(Ch + (size_t)row * DI + col) =
                pack2h(acc.a[ai][j][0] * qm0, acc.a[ai][j][1] * qm1);
            *(uint32_t*)(Ch + (size_t)(row + 8) * DI + col) =
                pack2h(acc.a[ai][j][2] * qm0, acc.a[ai][j][3] * qm1);
        }
    }
}

// output projection: fp32 out (Wout norm folded in attention)
__global__ void __launch_bounds__(128) gemm_out(float* __restrict__ C) {
    extern __shared__ char smem[];
    const uint32_t sb = smem_u32(smem);
    const int tid = threadIdx.x;
    const int wid = tid >> 5, lane = tid & 31;
    const int wm = wid >> 1, wn = wid & 1;
    const int mbase = blockIdx.y * 128, nbase = blockIdx.x * 128;

    GAcc acc;
    gemm_mainloop(g_o16, g_w16[3], sb, tid, mbase, nbase, acc);

    #pragma unroll
    for (int j = 0; j < 8; ++j) {
        const int col = nbase + wn * 64 + j * 8 + (lane & 3) * 2;
        #pragma unroll
        for (int ai = 0; ai < 4; ++ai) {
            const int row = mbase + wm * 64 + ai * 16 + (lane >> 2);
            *(float2*)(C + (size_t)row * DIM + col) =
                make_float2(acc.a[ai][j][0], acc.a[ai][j][1]);
            *(float2*)(C + (size_t)(row + 8) * DIM + col) =
                make_float2(acc.a[ai][j][2], acc.a[ai][j][3]);
        }
    }
}

// ============ fp16 causal flash attention (exp2 domain), dbl-buffered K/V ===
// 64x64 tiles, 128 thr / 4 warps, warp = 16 Q rows. Tiles 64 rows x 256B.
// (R8/R9/R12 version — best measured attention config.)
#define AQ 0
#define AKV 16384      /* buffer b at AKV + b*32768: K 16KB then V 16KB */
#define A_SMEM 81920

__global__ void __launch_bounds__(128) attn16() {
    extern __shared__ char asm_[];
    const uint32_t sb = smem_u32(asm_);
    const int tid = threadIdx.x;
    const int wid = tid >> 5, lane = tid & 31;
    const int qt = 31 - blockIdx.x;          // longest work first
    const int bh = blockIdx.y;
    const int b = bh >> 4, h = bh & 15;
    const size_t base = (size_t)b * SEQ * DI + (size_t)h * HD;
    const __half *qp = g_q16 + base;
    const __half *kp = g_k16 + base, *vp = g_v16 + base;

    // Q + (K,V) tile 0 in one group
    #pragma unroll
    for (int it = 0; it < 8; ++it) {
        const int i = tid + it * 128;
        const int r = i >> 4, c = i & 15;
        const uint32_t s = (r << 8) + ((c ^ (r & 7)) << 4);
        cp16(sb + AQ + s, qp + (size_t)(qt * 64 + r) * DI + c * 8);
        const size_t g0 = (size_t)r * DI + c * 8;    // K/V tile 0 rows
        cp16(sb + AKV + s, kp + g0);
        cp16(sb + AKV + 16384 + s, vp + g0);
    }
    CP_COMMIT();

    float oAcc[16][4];
    #pragma unroll
    for (int i = 0; i < 16; i++)
        #pragma unroll
        for (int j = 0; j < 4; j++) oAcc[i][j] = 0.f;
    float m0 = -1e30f, m1 = -1e30f, l0 = 0.f, l1 = 0.f;

    for (int kt = 0; kt <= qt; ++kt) {
        CP_WAIT(0);
        __syncthreads();
        if (kt < qt) {   // prefetch next K/V into other buffer
            const uint32_t dst = sb + AKV + ((kt + 1) & 1) * 32768;
            #pragma unroll
            for (int it = 0; it < 8; ++it) {
                const int i = tid + it * 128;
                const int r = i >> 4, c = i & 15;
                const size_t g = (size_t)((kt + 1) * 64 + r) * DI + c * 8;
                const uint32_t s = (r << 8) + ((c ^ (r & 7)) << 4);
                cp16(dst + s, kp + g);
                cp16(dst + 16384 + s, vp + g);
            }
            CP_COMMIT();
        }
        const uint32_t KB = sb + AKV + (kt & 1) * 32768;
        const uint32_t VB = KB + 16384;

        // ---- S = Q K^T (log2 domain via q scaling) ----
        float sAcc[8][4];
        #pragma unroll
        for (int i = 0; i < 8; i++)
            #pragma unroll
            for (int j = 0; j < 4; j++) sAcc[i][j] = 0.f;

        #pragma unroll
        for (int kk = 0; kk < 8; ++kk) {
            const int arow = wid * 16 + (lane & 15);
            const int achk = 2 * kk + (lane >> 4);
            const uint32_t aoff = (arow << 8) + ((achk ^ (arow & 7)) << 4);
            uint32_t qf[4];
            LDSM_X4(qf, sb + AQ + aoff);
            const int brow_ = (lane & 7) + ((lane >> 4) & 1) * 8;
            const int bchk = 2 * kk + ((lane >> 3) & 1);
            #pragma unroll
            for (int g = 0; g < 4; ++g) {
                const int brow = g * 16 + brow_;
                const uint32_t boff = (brow << 8) + ((bchk ^ (brow & 7)) << 4);
                uint32_t kf[4];
                LDSM_X4(kf, KB + boff);
                MMA16816H(sAcc[2 * g],     qf, kf[0], kf[1]);
                MMA16816H(sAcc[2 * g + 1], qf, kf[2], kf[3]);
            }
        }

        if (kt == qt) {   // causal mask on diagonal tile
            const int colb = (lane & 3) * 2;
            const int rowa = wid * 16 + (lane >> 2);
            #pragma unroll
            for (int jt = 0; jt < 8; ++jt) {
                const int c0 = jt * 8 + colb;
                if (c0 > rowa)     sAcc[jt][0] = -1e30f;
                if (c0 + 1 > rowa) sAcc[jt][1] = -1e30f;
                if (c0 > rowa + 8)     sAcc[jt][2] = -1e30f;
                if (c0 + 1 > rowa + 8) sAcc[jt][3] = -1e30f;
            }
        }

        // ---- online softmax in exp2 domain ----
        float mx0 = -1e30f, mx1 = -1e30f;
        #pragma unroll
        for (int jt = 0; jt < 8; ++jt) {
            mx0 = fmaxf(mx0, fmaxf(sAcc[jt][0], sAcc[jt][1]));
            mx1 = fmaxf(mx1, fmaxf(sAcc[jt][2], sAcc[jt][3]));
        }
        mx0 = fmaxf(mx0, __shfl_xor_sync(0xffffffffu, mx0, 1));
        mx0 = fmaxf(mx0, __shfl_xor_sync(0xffffffffu, mx0, 2));
        mx1 = fmaxf(mx1, __shfl_xor_sync(0xffffffffu, mx1, 1));
        mx1 = fmaxf(mx1, __shfl_xor_sync(0xffffffffu, mx1, 2));
        const float mn0 = fmaxf(m0, mx0), mn1 = fmaxf(m1, mx1);
        const float scl0 = ex2f(m0 - mn0), scl1 = ex2f(m1 - mn1);
        m0 = mn0; m1 = mn1;

        uint32_t ph[8][2];
        float rs0 = 0.f, rs1 = 0.f;
        #pragma unroll
        for (int jt = 0; jt < 8; ++jt) {
            const float p0 = ex2f(sAcc[jt][0] - mn0);
            const float p1 = ex2f(sAcc[jt][1] - mn0);
            const float p2 = ex2f(sAcc[jt][2] - mn1);
            const float p3 = ex2f(sAcc[jt][3] - mn1);
            rs0 += p0 + p1;
            rs1 += p2 + p3;
            ph[jt][0] = pack2h(p0, p1);
            ph[jt][1] = pack2h(p2, p3);
        }
        rs0 += __shfl_xor_sync(0xffffffffu, rs0, 1);
        rs0 += __shfl_xor_sync(0xffffffffu, rs0, 2);
        rs1 += __shfl_xor_sync(0xffffffffu, rs1, 1);
        rs1 += __shfl_xor_sync(0xffffffffu, rs1, 2);
        l0 = l0 * scl0 + rs0;
        l1 = l1 * scl1 + rs1;
        #pragma unroll
        for (int dt = 0; dt < 16; ++dt) {
            oAcc[dt][0] *= scl0; oAcc[dt][1] *= scl0;
            oAcc[dt][2] *= scl1; oAcc[dt][3] *= scl1;
        }

        // ---- O += P V (V via ldmatrix.trans) ----
        #pragma unroll
        for (int t = 0; t < 4; ++t) {
            uint32_t pa[4] = {ph[2 * t][0], ph[2 * t][1], ph[2 * t + 1][0], ph[2 * t + 1][1]};
            const int vrow = t * 16 + (lane & 7) + ((lane >> 3) & 1) * 8;
            #pragma unroll
            for (int g = 0; g < 8; ++g) {
                const int vchk = 2 * g + (lane >> 4);
                const uint32_t voff = (vrow << 8) + ((vchk ^ (vrow & 7)) << 4);
                uint32_t vf[4];
                LDSM_X4_T(vf, VB + voff);
                MMA16816H(oAcc[2 * g],     pa, vf[0], vf[1]);
                MMA16816H(oAcc[2 * g + 1], pa, vf[2], vf[3]);
            }
        }
    }

    // ---- epilogue: /l, fold Wout col-norm, emit fp16 ----
    const float li0 = 1.f / l0, li1 = 1.f / l1;
    const int row0 = qt * 64 + wid * 16 + (lane >> 2);
    const int colb = (lane & 3) * 2;
    __half* op = g_o16 + base;
    #pragma unroll
    for (int dt = 0; dt < 16; ++dt) {
        const int d = dt * 8 + colb;
        const float2 ro = *(const float2*)&g_rinv[3][h * HD + d];
        *(uint32_t*)(op + (size_t)row0 * DI + d) =
            pack2h(oAcc[dt][0] * li0 * ro.x, oAcc[dt][1] * li0 * ro.y);
        *(uint32_t*)(op + (size_t)(row0 + 8) * DI + d) =
            pack2h(oAcc[dt][2] * li1 * ro.x, oAcc[dt][3] * li1 * ro.y);
    }
}

// ============================== host side ====================================
extern "C" void kernel_launch(void* const* d_in, const int* in_sizes, int n_in,
                              void* d_out, int out_size) {
    (void)in_sizes; (void)n_in; (void)out_size;
    const float* x    = (const float*)d_in[0];
    const float* Wq   = (const float*)d_in[1];
    const float* Wk   = (const float*)d_in[2];
    const float* Wv   = (const float*)d_in[3];
    const float* Wout = (const float*)d_in[4];
    const float* qk   = (const float*)d_in[5];
    float* out = (float*)d_out;

    const int gsmem = 3 * GS_STAGE;   // 96KB
    cudaFuncSetAttribute(gemm_qkv, cudaFuncAttributeMaxDynamicSharedMemorySize, gsmem);
    cudaFuncSetAttribute(gemm_out, cudaFuncAttributeMaxDynamicSharedMemorySize, gsmem);
    cudaFuncSetAttribute(attn16, cudaFuncAttributeMaxDynamicSharedMemorySize, A_SMEM);

    // 0-1: fused prep (converts + row norms + colnorm partials), then fin
    prep_fused<<<18560, 256>>>(x, Wq, Wk, Wv, Wout);
    colnorm_fin<<<DIM / 256, 256>>>();

    // 2: merged QKV projection (single launch, 64x64 warp tiles)
    gemm_qkv<<<dim3(DI / 128, MTOT / 128, 3), 128, gsmem>>>(qk);

    // 3: attention (64-row CTAs, 2 CTA/SM — best measured config)
    attn16<<<dim3(SEQ / 64, BATCH * HEADS), 128, A_SMEM>>>();

    // 4: output projection
    gemm_out<<<dim3(DIM / 128, MTOT / 128), 128, gsmem>>>(out);
}

// round 14
// speedup vs baseline: 1.0405x; 1.0405x over previous
#include <cuda_runtime.h>
#include <cuda_fp16.h>
#include <math.h>
#include <stdint.h>

#define BATCH 2
#define SEQ 2048
#define DIM 2048
#define HEADS 16
#define HD 128
#define DI 2048           /* HEADS*HD */
#define MTOT (BATCH*SEQ)  /* 4096 */

// ---------------- scratch (device globals: allocation-free rule) ------------
__device__ float g_rinv[4][DIM];     // 0:Wq rows 1:Wk rows 2:Wv rows 3:Wout cols
__device__ float g_colpart[16][DIM];
__device__ __half g_x16[(size_t)MTOT * DIM];
__device__ __half g_w16[4][(size_t)DIM * DIM];   // q,k,v,out
__device__ __half g_q16[(size_t)MTOT * DI];
__device__ __half g_k16[(size_t)MTOT * DI];
__device__ __half g_v16[(size_t)MTOT * DI];
__device__ __half g_o16[(size_t)MTOT * DI];

// ============================ PTX helpers (sm_80+ portable) =================
__device__ __forceinline__ uint32_t smem_u32(const void* p) {
    uint32_t a;
    asm("{ .reg .u64 t; cvta.to.shared.u64 t, %1; cvt.u32.u64 %0, t; }"
        : "=r"(a) : "l"(p));
    return a;
}

__device__ __forceinline__ void cp16(uint32_t saddr, const void* g) {
    asm volatile("cp.async.cg.shared.global [%0], [%1], 16;"
                 :: "r"(saddr), "l"(g) : "memory");
}
#define CP_COMMIT() asm volatile("cp.async.commit_group;" ::: "memory")
#define CP_WAIT(n)  asm volatile("cp.async.wait_group %0;" :: "n"(n) : "memory")

#define LDSM_X4(r, addr) \
    asm volatile("ldmatrix.sync.aligned.m8n8.x4.shared.b16 {%0,%1,%2,%3}, [%4];" \
        : "=r"((r)[0]), "=r"((r)[1]), "=r"((r)[2]), "=r"((r)[3]) : "r"(addr))

#define LDSM_X4_T(r, addr) \
    asm volatile("ldmatrix.sync.aligned.m8n8.x4.trans.shared.b16 {%0,%1,%2,%3}, [%4];" \
        : "=r"((r)[0]), "=r"((r)[1]), "=r"((r)[2]), "=r"((r)[3]) : "r"(addr))

#define MMA16816H(d, a, b0, b1) \
    asm volatile("mma.sync.aligned.m16n8k16.row.col.f32.f16.f16.f32 " \
        "{%0,%1,%2,%3}, {%4,%5,%6,%7}, {%8,%9}, {%0,%1,%2,%3};" \
        : "+f"((d)[0]), "+f"((d)[1]), "+f"((d)[2]), "+f"((d)[3]) \
        : "r"((a)[0]), "r"((a)[1]), "r"((a)[2]), "r"((a)[3]), "r"(b0), "r"(b1))

__device__ __forceinline__ uint32_t pack2h(float a, float b) {
    uint32_t r;
    asm("cvt.rn.f16x2.f32 %0, %1, %2;" : "=r"(r) : "f"(b), "f"(a));
    return r;
}
__device__ __forceinline__ float ex2f(float x) {
    float r;
    asm("ex2.approx.ftz.f32 %0, %1;" : "=f"(r) : "f"(x));
    return r;
}
__device__ __forceinline__ uint32_t ex2h2(uint32_t x) {
    uint32_t r;
    asm("ex2.approx.f16x2 %0, %1;" : "=r"(r) : "r"(x));
    return r;
}

// =================== fused prep: all converts + norms in ONE kernel ==========
__global__ void __launch_bounds__(256) prep_fused(
    const float* __restrict__ x, const float* __restrict__ Wq,
    const float* __restrict__ Wk, const float* __restrict__ Wv,
    const float* __restrict__ Wout)
{
    __shared__ float red[8];
    const int bid = blockIdx.x, tid = threadIdx.x;
    if (bid < 8192) {                       // x convert
        const int i = bid * 256 + tid;
        float4 v = ((const float4*)x)[i];
        uint32_t* o = (uint32_t*)g_x16;
        o[2 * i] = pack2h(v.x, v.y);
        o[2 * i + 1] = pack2h(v.z, v.w);
    } else if (bid < 14336) {               // Wq/Wk/Wv rows + norms
        const int t = bid - 8192;
        const int sel = t >> 11, row = t & 2047;
        const float* W = sel == 0 ? Wq : (sel == 1 ? Wk : Wv);
        const float4* p = (const float4*)(W + (size_t)row * DIM);
        uint32_t* op = (uint32_t*)(&g_w16[sel][(size_t)row * DIM]);
        float s = 0.f;
        #pragma unroll
        for (int i = tid; i < DIM / 4; i += 256) {
            float4 v = p[i];
            s += v.x * v.x + v.y * v.y + v.z * v.z + v.w * v.w;
            op[2 * i] = pack2h(v.x, v.y);
            op[2 * i + 1] = pack2h(v.z, v.w);
        }
        #pragma unroll
        for (int off = 16; off; off >>= 1) s += __shfl_xor_sync(0xffffffffu, s, off);
        if ((tid & 31) == 0) red[tid >> 5] = s;
        __syncthreads();
        if (tid == 0) {
            float tt = 0.f;
            #pragma unroll
            for (int i = 0; i < 8; i++) tt += red[i];
            g_rinv[sel][row] = 1.f / fmaxf(sqrtf(tt), 1e-12f);
        }
    } else if (bid < 18432) {               // Wout convert
        const int i = (bid - 14336) * 256 + tid;
        float4 v = ((const float4*)Wout)[i];
        uint32_t* o = (uint32_t*)(&g_w16[3][0]);
        o[2 * i] = pack2h(v.x, v.y);
        o[2 * i + 1] = pack2h(v.z, v.w);
    } else {                                 // colnorm partials
        const int t = bid - 18432;           // 0..127
        const int col = (t & 7) * 256 + tid;
        const int r0 = (t >> 3) * 128;
        float s = 0.f;
        for (int r = 0; r < 128; ++r) {
            float v = Wout[(size_t)(r0 + r) * DI + col];
            s += v * v;
        }
        g_colpart[t >> 3][col] = s;
    }
}

__global__ void colnorm_fin() {
    int c = blockIdx.x * 256 + threadIdx.x;
    float s = 0.f;
    #pragma unroll
    for (int i = 0; i < 16; ++i) s += g_colpart[i][c];
    g_rinv[3][c] = 1.f / fmaxf(sqrtf(s), 1e-12f);
}

// =================== fp16 single-pass NT GEMM, 128x128x64 tiles ==============
// 256 thr / 8 warps (wm 0..3 x wn 0..1), warp tile 32x64, 3-stage cp.async,
// 2 CTA/SM, one sync per k-tile. (R8/R12 mainloop — best measured config.)
#define GS_MAT 16384
#define GS_STAGE 32768
#define GS_NKT (DIM / 64)   /* 32 */

struct GAcc { float a[2][8][4]; };

__device__ __forceinline__ void gemm_mainloop(
    const __half* __restrict__ Ag, const __half* __restrict__ Bg,
    uint32_t sb, int tid, int mbase, int nbase, GAcc& acc)
{
    const int wid = tid >> 5, lane = tid & 31;
    const int wm = wid & 3, wn = wid >> 2;

    auto load_stage = [&](int kt, int buf) {
        const uint32_t st = sb + buf * GS_STAGE;
        const int koff = kt * 64;
        #pragma unroll
        for (int h = 0; h < 4; ++h) {
            const int cid = tid + h * 256;
            const int r = cid >> 3, c = cid & 7;
            const uint32_t aoff = ((c >> 1) << 12) + ((r >> 4) << 9) +
                (((r & 7) + ((r >> 3) & 1) * 8 + (c & 1) * 16) << 4);
            const uint32_t boff = ((c >> 1) << 12) + ((r >> 4) << 9) +
                (((r & 7) + (c & 1) * 8 + ((r >> 3) & 1) * 16) << 4);
            cp16(st + aoff, Ag + (size_t)(mbase + r) * DIM + koff + c * 8);
            cp16(st + GS_MAT + boff, Bg + (size_t)(nbase + r) * DIM + koff + c * 8);
        }
    };

    #pragma unroll
    for (int i = 0; i < 2; i++)
        #pragma unroll
        for (int j = 0; j < 8; j++)
            #pragma unroll
            for (int t = 0; t < 4; t++) acc.a[i][j][t] = 0.f;

    load_stage(0, 0); CP_COMMIT();
    load_stage(1, 1); CP_COMMIT();

    for (int kt = 0; kt < GS_NKT; ++kt) {
        CP_WAIT(1);          // stage kt complete
        __syncthreads();     // visible; compute(kt-1) done
        if (kt + 2 < GS_NKT) load_stage(kt + 2, (kt + 2) % 3);
        CP_COMMIT();         // always commit (empty ok)
        const uint32_t stg = sb + (kt % 3) * GS_STAGE;
        #pragma unroll
        for (int s = 0; s < 4; ++s) {   // four k16 slabs per k-tile
            const uint32_t aA = stg + (s << 12) + ((wm * 2) << 9) + lane * 16;
            const uint32_t bA = stg + GS_MAT + (s << 12) + ((wn * 4) << 9) + lane * 16;
            uint32_t a0[4], a1[4], b[4][4];
            LDSM_X4(a0, aA);
            LDSM_X4(a1, aA + 512);
            #pragma unroll
            for (int jt = 0; jt < 4; ++jt) LDSM_X4(b[jt], bA + jt * 512);
            #pragma unroll
            for (int jt = 0; jt < 4; ++jt) {
                MMA16816H(acc.a[0][2 * jt],     a0, b[jt][0], b[jt][1]);
                MMA16816H(acc.a[0][2 * jt + 1], a0, b[jt][2], b[jt][3]);
                MMA16816H(acc.a[1][2 * jt],     a1, b[jt][0], b[jt][1]);
                MMA16816H(acc.a[1][2 * jt + 1], a1, b[jt][2], b[jt][3]);
            }
        }
    }
    __syncthreads();
}

// merged QKV projection: blockIdx.z selects weight + epilogue flavor.
__global__ void __launch_bounds__(256) gemm_qkv(const float* __restrict__ qks) {
    extern __shared__ char smem[];
    const uint32_t sb = smem_u32(smem);
    const int tid = threadIdx.x;
    const int wid = tid >> 5, lane = tid & 31;
    const int wm = wid & 3, wn = wid >> 2;
    const int mbase = blockIdx.y * 128, nbase = blockIdx.x * 128;
    const int sel = blockIdx.z;

    GAcc acc;
    gemm_mainloop(g_x16, g_w16[sel], sb, tid, mbase, nbase, acc);

    const int lr0 = wm * 32 + (lane >> 2);
    {
        const float* rinv = g_rinv[sel];
        #pragma unroll
        for (int j = 0; j < 8; ++j) {
            const int col = nbase + wn * 64 + j * 8 + (lane & 3) * 2;
            const float s0 = rinv[col], s1 = rinv[col + 1];
            #pragma unroll
            for (int i = 0; i < 2; ++i) {
                acc.a[i][j][0] *= s0; acc.a[i][j][1] *= s1;
                acc.a[i][j][2] *= s0; acc.a[i][j][3] *= s1;
            }
        }
    }
    if (sel < 2) {
        // per-row l2 norm over this CTA's 128 cols (= one head)
        float ssq[4] = {0.f, 0.f, 0.f, 0.f};
        #pragma unroll
        for (int i = 0; i < 2; ++i)
            #pragma unroll
            for (int j = 0; j < 8; ++j) {
                ssq[2 * i]     += acc.a[i][j][0] * acc.a[i][j][0] + acc.a[i][j][1] * acc.a[i][j][1];
                ssq[2 * i + 1] += acc.a[i][j][2] * acc.a[i][j][2] + acc.a[i][j][3] * acc.a[i][j][3];
            }
        #pragma unroll
        for (int r = 0; r < 4; ++r) {
            ssq[r] += __shfl_xor_sync(0xffffffffu, ssq[r], 1);
            ssq[r] += __shfl_xor_sync(0xffffffffu, ssq[r], 2);
        }
        float* red = (float*)smem;   // reuse pipeline smem: [2][128]
        if ((lane & 3) == 0) {
            #pragma unroll
            for (int r = 0; r < 4; ++r)
                red[wn * 128 + lr0 + (r & 1) * 8 + (r >> 1) * 16] = ssq[r];
        }
        __syncthreads();
        float rn_[4];
        #pragma unroll
        for (int r = 0; r < 4; ++r) {
            const int lr = lr0 + (r & 1) * 8 + (r >> 1) * 16;
            rn_[r] = 1.f / fmaxf(sqrtf(red[lr] + red[128 + lr]), 1e-12f);
        }
        #pragma unroll
        for (int i = 0; i < 2; ++i)
            #pragma unroll
            for (int j = 0; j < 8; ++j) {
                acc.a[i][j][0] *= rn_[2 * i];     acc.a[i][j][1] *= rn_[2 * i];
                acc.a[i][j][2] *= rn_[2 * i + 1]; acc.a[i][j][3] *= rn_[2 * i + 1];
            }
    }
    __half* Ch = sel == 0 ? g_q16 : (sel == 1 ? g_k16 : g_v16);
    #pragma unroll
    for (int j = 0; j < 8; ++j) {
        const int col = nbase + wn * 64 + j * 8 + (lane & 3) * 2;
        float qm0 = 1.f, qm1 = 1.f;
        if (sel == 0) {
            // DIM * sqrt(HD) * log2(e)  (softmax uses ex2)
            const float C = 23170.475005920826f * 1.4426950408889634f;
            qm0 = qks[col] * C;
            qm1 = qks[col + 1] * C;
        }
        #pragma unroll
        for (int i = 0; i < 2; ++i) {
            const int row = mbase + lr0 + i * 16;
            *(uint32_t*)(Ch + (size_t)row * DI + col) =
                pack2h(acc.a[i][j][0] * qm0, acc.a[i][j][1] * qm1);
            *(uint32_t*)(Ch + (size_t)(row + 8) * DI + col) =
                pack2h(acc.a[i][j][2] * qm0, acc.a[i][j][3] * qm1);
        }
    }
}

// output projection: fp32 out (Wout norm folded in attention)
__global__ void __launch_bounds__(256) gemm_out(float* __restrict__ C) {
    extern __shared__ char smem[];
    const uint32_t sb = smem_u32(smem);
    const int tid = threadIdx.x;
    const int wid = tid >> 5, lane = tid & 31;
    const int wm = wid & 3, wn = wid >> 2;
    const int mbase = blockIdx.y * 128, nbase = blockIdx.x * 128;

    GAcc acc;
    gemm_mainloop(g_o16, g_w16[3], sb, tid, mbase, nbase, acc);

    const int lr0 = wm * 32 + (lane >> 2);
    #pragma unroll
    for (int j = 0; j < 8; ++j) {
        const int col = nbase + wn * 64 + j * 8 + (lane & 3) * 2;
        #pragma unroll
        for (int i = 0; i < 2; ++i) {
            const int row = mbase + lr0 + i * 16;
            *(float2*)(C + (size_t)row * DIM + col) =
                make_float2(acc.a[i][j][0], acc.a[i][j][1]);
            *(float2*)(C + (size_t)(row + 8) * DIM + col) =
                make_float2(acc.a[i][j][2], acc.a[i][j][3]);
        }
    }
}

// ============ fp16 causal flash attention (exp2 domain), dbl-buffered K/V ===
// 64x64 tiles, 128 thr / 4 warps, warp = 16 Q rows. P via ex2.approx.f16x2
// (half the MUFU ops; p emerges pre-packed for the PV MMA).
#define AQ 0
#define AKV 16384      /* buffer b at AKV + b*32768: K 16KB then V 16KB */
#define A_SMEM 81920

__global__ void __launch_bounds__(128) attn16() {
    extern __shared__ char asm_[];
    const uint32_t sb = smem_u32(asm_);
    const int tid = threadIdx.x;
    const int wid = tid >> 5, lane = tid & 31;
    const int qt = 31 - blockIdx.x;          // longest work first
    const int bh = blockIdx.y;
    const int b = bh >> 4, h = bh & 15;
    const size_t base = (size_t)b * SEQ * DI + (size_t)h * HD;
    const __half *qp = g_q16 + base;
    const __half *kp = g_k16 + base, *vp = g_v16 + base;

    // Q + (K,V) tile 0 in one group
    #pragma unroll
    for (int it = 0; it < 8; ++it) {
        const int i = tid + it * 128;
        const int r = i >> 4, c = i & 15;
        const uint32_t s = (r << 8) + ((c ^ (r & 7)) << 4);
        cp16(sb + AQ + s, qp + (size_t)(qt * 64 + r) * DI + c * 8);
        const size_t g0 = (size_t)r * DI + c * 8;    // K/V tile 0 rows
        cp16(sb + AKV + s, kp + g0);
        cp16(sb + AKV + 16384 + s, vp + g0);
    }
    CP_COMMIT();

    float oAcc[16][4];
    #pragma unroll
    for (int i = 0; i < 16; i++)
        #pragma unroll
        for (int j = 0; j < 4; j++) oAcc[i][j] = 0.f;
    float m0 = -1e30f, m1 = -1e30f, l0 = 0.f, l1 = 0.f;

    for (int kt = 0; kt <= qt; ++kt) {
        CP_WAIT(0);
        __syncthreads();
        if (kt < qt) {   // prefetch next K/V into other buffer
            const uint32_t dst = sb + AKV + ((kt + 1) & 1) * 32768;
            #pragma unroll
            for (int it = 0; it < 8; ++it) {
                const int i = tid + it * 128;
                const int r = i >> 4, c = i & 15;
                const size_t g = (size_t)((kt + 1) * 64 + r) * DI + c * 8;
                const uint32_t s = (r << 8) + ((c ^ (r & 7)) << 4);
                cp16(dst + s, kp + g);
                cp16(dst + 16384 + s, vp + g);
            }
            CP_COMMIT();
        }
        const uint32_t KB = sb + AKV + (kt & 1) * 32768;
        const uint32_t VB = KB + 16384;

        // ---- S = Q K^T (log2 domain via q scaling) ----
        float sAcc[8][4];
        #pragma unroll
        for (int i = 0; i < 8; i++)
            #pragma unroll
            for (int j = 0; j < 4; j++) sAcc[i][j] = 0.f;

        #pragma unroll
        for (int kk = 0; kk < 8; ++kk) {
            const int arow = wid * 16 + (lane & 15);
            const int achk = 2 * kk + (lane >> 4);
            const uint32_t aoff = (arow << 8) + ((achk ^ (arow & 7)) << 4);
            uint32_t qf[4];
            LDSM_X4(qf, sb + AQ + aoff);
            const int brow_ = (lane & 7) + ((lane >> 4) & 1) * 8;
            const int bchk = 2 * kk + ((lane >> 3) & 1);
            #pragma unroll
            for (int g = 0; g < 4; ++g) {
                const int brow = g * 16 + brow_;
                const uint32_t boff = (brow << 8) + ((bchk ^ (brow & 7)) << 4);
                uint32_t kf[4];
                LDSM_X4(kf, KB + boff);
                MMA16816H(sAcc[2 * g],     qf, kf[0], kf[1]);
                MMA16816H(sAcc[2 * g + 1], qf, kf[2], kf[3]);
            }
        }

        if (kt == qt) {   // causal mask on diagonal tile
            const int colb = (lane & 3) * 2;
            const int rowa = wid * 16 + (lane >> 2);
            #pragma unroll
            for (int jt = 0; jt < 8; ++jt) {
                const int c0 = jt * 8 + colb;
                if (c0 > rowa)     sAcc[jt][0] = -1e30f;
                if (c0 + 1 > rowa) sAcc[jt][1] = -1e30f;
                if (c0 > rowa + 8)     sAcc[jt][2] = -1e30f;
                if (c0 + 1 > rowa + 8) sAcc[jt][3] = -1e30f;
            }
        }

        // ---- online softmax in exp2 domain ----
        float mx0 = -1e30f, mx1 = -1e30f;
        #pragma unroll
        for (int jt = 0; jt < 8; ++jt) {
            mx0 = fmaxf(mx0, fmaxf(sAcc[jt][0], sAcc[jt][1]));
            mx1 = fmaxf(mx1, fmaxf(sAcc[jt][2], sAcc[jt][3]));
        }
        mx0 = fmaxf(mx0, __shfl_xor_sync(0xffffffffu, mx0, 1));
        mx0 = fmaxf(mx0, __shfl_xor_sync(0xffffffffu, mx0, 2));
        mx1 = fmaxf(mx1, __shfl_xor_sync(0xffffffffu, mx1, 1));
        mx1 = fmaxf(mx1, __shfl_xor_sync(0xffffffffu, mx1, 2));
        const float mn0 = fmaxf(m0, mx0), mn1 = fmaxf(m1, mx1);
        const float scl0 = ex2f(m0 - mn0), scl1 = ex2f(m1 - mn1);
        m0 = mn0; m1 = mn1;

        // P = 2^(s-m) via packed fp16 ex2 (one MUFU op per pair).
        // Row max gives p_max = 1 exactly; masked -1e30 -> -inf -> p = 0.
        uint32_t ph[8][2];
        float rs0 = 0.f, rs1 = 0.f;
        #pragma unroll
        for (int jt = 0; jt < 8; ++jt) {
            ph[jt][0] = ex2h2(pack2h(sAcc[jt][0] - mn0, sAcc[jt][1] - mn0));
            ph[jt][1] = ex2h2(pack2h(sAcc[jt][2] - mn1, sAcc[jt][3] - mn1));
            const float2 f0 = __half22float2(*(__half2*)&ph[jt][0]);
            const float2 f1 = __half22float2(*(__half2*)&ph[jt][1]);
            rs0 += f0.x + f0.y;
            rs1 += f1.x + f1.y;
        }
        rs0 += __shfl_xor_sync(0xffffffffu, rs0, 1);
        rs0 += __shfl_xor_sync(0xffffffffu, rs0, 2);
        rs1 += __shfl_xor_sync(0xffffffffu, rs1, 1);
        rs1 += __shfl_xor_sync(0xffffffffu, rs1, 2);
        l0 = l0 * scl0 + rs0;
        l1 = l1 * scl1 + rs1;
        #pragma unroll
        for (int dt = 0; dt < 16; ++dt) {
            oAcc[dt][0] *= scl0; oAcc[dt][1] *= scl0;
            oAcc[dt][2] *= scl1; oAcc[dt][3] *= scl1;
        }

        // ---- O += P V (V via ldmatrix.trans) ----
        #pragma unroll
        for (int t = 0; t < 4; ++t) {
            uint32_t pa[4] = {ph[2 * t][0], ph[2 * t][1], ph[2 * t + 1][0], ph[2 * t + 1][1]};
            const int vrow = t * 16 + (lane & 7) + ((lane >> 3) & 1) * 8;
            #pragma unroll
            for (int g = 0; g < 8; ++g) {
                const int vchk = 2 * g + (lane >> 4);
                const uint32_t voff = (vrow << 8) + ((vchk ^ (vrow & 7)) << 4);
                uint32_t vf[4];
                LDSM_X4_T(vf, VB + voff);
                MMA16816H(oAcc[2 * g],     pa, vf[0], vf[1]);
                MMA16816H(oAcc[2 * g + 1], pa, vf[2], vf[3]);
            }
        }
    }

    // ---- epilogue: /l, fold Wout col-norm, emit fp16 ----
    const float li0 = 1.f / l0, li1 = 1.f / l1;
    const int row0 = qt * 64 + wid * 16 + (lane >> 2);
    const int colb = (lane & 3) * 2;
    __half* op = g_o16 + base;
    #pragma unroll
    for (int dt = 0; dt < 16; ++dt) {
        const int d = dt * 8 + colb;
        const float2 ro = *(const float2*)&g_rinv[3][h * HD + d];
        *(uint32_t*)(op + (size_t)row0 * DI + d) =
            pack2h(oAcc[dt][0] * li0 * ro.x, oAcc[dt][1] * li0 * ro.y);
        *(uint32_t*)(op + (size_t)(row0 + 8) * DI + d) =
            pack2h(oAcc[dt][2] * li1 * ro.x, oAcc[dt][3] * li1 * ro.y);
    }
}

// ============================== host side ====================================
extern "C" void kernel_launch(void* const* d_in, const int* in_sizes, int n_in,
                              void* d_out, int out_size) {
    (void)in_sizes; (void)n_in; (void)out_size;
    const float* x    = (const float*)d_in[0];
    const float* Wq   = (const float*)d_in[1];
    const float* Wk   = (const float*)d_in[2];
    const float* Wv   = (const float*)d_in[3];
    const float* Wout = (const float*)d_in[4];
    const float* qk   = (const float*)d_in[5];
    float* out = (float*)d_out;

    const int gsmem = 3 * GS_STAGE;   // 96KB
    cudaFuncSetAttribute(gemm_qkv, cudaFuncAttributeMaxDynamicSharedMemorySize, gsmem);
    cudaFuncSetAttribute(gemm_out, cudaFuncAttributeMaxDynamicSharedMemorySize, gsmem);
    cudaFuncSetAttribute(attn16, cudaFuncAttributeMaxDynamicSharedMemorySize, A_SMEM);

    // 0-1: fused prep (converts + row norms + colnorm partials), then fin
    prep_fused<<<18560, 256>>>(x, Wq, Wk, Wv, Wout);
    colnorm_fin<<<DIM / 256, 256>>>();

    // 2: merged QKV projection (single launch — avoids wave-tail quantization)
    gemm_qkv<<<dim3(DI / 128, MTOT / 128, 3), 256, gsmem>>>(qk);

    // 3: attention (64-row CTAs, 2 CTA/SM — best measured config)
    attn16<<<dim3(SEQ / 64, BATCH * HEADS), 128, A_SMEM>>>();

    // 4: output projection
    gemm_out<<<dim3(DIM / 128, MTOT / 128), 256, gsmem>>>(out);
}